// round 1
// baseline (speedup 1.0000x reference)
#include <cuda_runtime.h>
#include <math.h>

// Problem constants
#define BB 2
#define TT 2048
#define DD 1024
#define NH 16
#define HD 64
#define MTOT 4096           // BB*TT
#define LOG2E_ 1.442695041f

// Scratch buffers (allocation-free rule: __device__ globals)
__device__ float g_q[4194304];     // [B,T,N,H] = [4096,1024]
__device__ float g_k[4194304];
__device__ float g_v[4194304];
__device__ float g_attn[4194304];

// ---------------------------------------------------------------------------
// Fused QKV projection GEMM (NN): C = X @ W + bias, with per-dim scale on Q.
// X: [4096,1024], W: [1024,1024] (cols = n*H+h). blockIdx.z selects Q/K/V.
// 128x128 block tile, BK=16, 8x8 microtile, 256 threads.
// ---------------------------------------------------------------------------
__global__ __launch_bounds__(256) void qkv_gemm_kernel(
    const float* __restrict__ X,
    const float* __restrict__ Wq, const float* __restrict__ Wk, const float* __restrict__ Wv,
    const float* __restrict__ Bq, const float* __restrict__ Bk, const float* __restrict__ Bv,
    const float* __restrict__ pds)
{
    __shared__ float As[16][132];   // A^T tile, padded
    __shared__ float Bs[16][128];

    const int z = blockIdx.z;
    const float* __restrict__ W    = (z == 0) ? Wq : (z == 1) ? Wk : Wv;
    const float* __restrict__ bias = (z == 0) ? Bq : (z == 1) ? Bk : Bv;
    float* __restrict__ C          = (z == 0) ? g_q : (z == 1) ? g_k : g_v;

    const int tid = threadIdx.x;
    const int tx = tid & 15, ty = tid >> 4;
    const int row0 = blockIdx.y * 128;
    const int col0 = blockIdx.x * 128;

    float acc[8][8];
#pragma unroll
    for (int i = 0; i < 8; ++i)
#pragma unroll
        for (int j = 0; j < 8; ++j) acc[i][j] = 0.f;

    for (int k0 = 0; k0 < 1024; k0 += 16) {
#pragma unroll
        for (int it = 0; it < 2; ++it) {
            int idx = tid + it * 256;           // 0..511
            int ar = idx >> 2, ak = (idx & 3) << 2;
            float4 a = *(const float4*)&X[(row0 + ar) * 1024 + k0 + ak];
            As[ak + 0][ar] = a.x; As[ak + 1][ar] = a.y;
            As[ak + 2][ar] = a.z; As[ak + 3][ar] = a.w;
            int bk = idx >> 5, bn = (idx & 31) << 2;
            *(float4*)&Bs[bk][bn] = *(const float4*)&W[(k0 + bk) * 1024 + col0 + bn];
        }
        __syncthreads();
#pragma unroll
        for (int kk = 0; kk < 16; ++kk) {
            float a[8], b[8];
            *(float4*)&a[0] = *(const float4*)&As[kk][ty * 8];
            *(float4*)&a[4] = *(const float4*)&As[kk][ty * 8 + 4];
            *(float4*)&b[0] = *(const float4*)&Bs[kk][tx * 8];
            *(float4*)&b[4] = *(const float4*)&Bs[kk][tx * 8 + 4];
#pragma unroll
            for (int i = 0; i < 8; ++i)
#pragma unroll
                for (int j = 0; j < 8; ++j)
                    acc[i][j] = fmaf(a[i], b[j], acc[i][j]);
        }
        __syncthreads();
    }

    // epilogue: bias, and per-dim query scale for z==0
    float bb[8], sc[8];
#pragma unroll
    for (int j = 0; j < 8; ++j) {
        int col = col0 + tx * 8 + j;
        bb[j] = bias[col];
        if (z == 0) {
            float p  = pds[col & 63];
            float sp = (p > 20.f) ? p : log1pf(__expf(p));
            sc[j] = (LOG2E_ * 0.125f) * sp;     // log2e / sqrt(64) * softplus
        } else {
            sc[j] = 1.f;
        }
    }
#pragma unroll
    for (int i = 0; i < 8; ++i) {
        int row = row0 + ty * 8 + i;
        float o[8];
#pragma unroll
        for (int j = 0; j < 8; ++j) o[j] = (acc[i][j] + bb[j]) * sc[j];
        *(float4*)&C[row * 1024 + col0 + tx * 8]     = make_float4(o[0], o[1], o[2], o[3]);
        *(float4*)&C[row * 1024 + col0 + tx * 8 + 4] = make_float4(o[4], o[5], o[6], o[7]);
    }
}

// ---------------------------------------------------------------------------
// Flash attention: one block per (b, n, 64 query rows). 256 threads (16x16),
// 4x4 microtiles for both S=QK^T and O=PV. Online softmax. Mask from gmem.
// Dynamic smem: sQ^T[64][68], sK^T[64][68], sV[64][64], sP^T[64][68].
// ---------------------------------------------------------------------------
__global__ __launch_bounds__(256) void attn_kernel(const int* __restrict__ mask)
{
    extern __shared__ float sm[];
    float* sQ = sm;                    // [h][r], stride 68
    float* sK = sQ + 64 * 68;          // [h][s], stride 68
    float* sV = sK + 64 * 68;          // [s][h], stride 64
    float* sP = sV + 64 * 64;          // [s][r], stride 68

    const int tid = threadIdx.x;
    const int tx = tid & 15, ty = tid >> 4;
    const int qt = blockIdx.x;         // 0..31
    const int n  = blockIdx.y;
    const int b  = blockIdx.z;
    const int q0 = qt * 64;

    // Load Q tile (transposed into sQ)
#pragma unroll
    for (int it = 0; it < 4; ++it) {
        int idx = tid + it * 256;      // 0..1023
        int r = idx >> 4, h4 = (idx & 15) << 2;
        float4 qv = *(const float4*)&g_q[((b * TT + q0 + r) * NH + n) * HD + h4];
        sQ[(h4 + 0) * 68 + r] = qv.x; sQ[(h4 + 1) * 68 + r] = qv.y;
        sQ[(h4 + 2) * 68 + r] = qv.z; sQ[(h4 + 3) * 68 + r] = qv.w;
    }

    float m_i[4], l_i[4], acc[4][4];
#pragma unroll
    for (int i = 0; i < 4; ++i) {
        m_i[i] = -3.0e38f; l_i[i] = 0.f;
#pragma unroll
        for (int j = 0; j < 4; ++j) acc[i][j] = 0.f;
    }
    __syncthreads();

    for (int st = 0; st < TT / 64; ++st) {
        const int s0 = st * 64;
        // Load K (transposed) and V tiles
#pragma unroll
        for (int it = 0; it < 4; ++it) {
            int idx = tid + it * 256;
            int s = idx >> 4, h4 = (idx & 15) << 2;
            int g = ((b * TT + s0 + s) * NH + n) * HD + h4;
            float4 kv = *(const float4*)&g_k[g];
            sK[(h4 + 0) * 68 + s] = kv.x; sK[(h4 + 1) * 68 + s] = kv.y;
            sK[(h4 + 2) * 68 + s] = kv.z; sK[(h4 + 3) * 68 + s] = kv.w;
            float4 vv = *(const float4*)&g_v[g];
            *(float4*)&sV[s * 64 + h4] = vv;
        }
        __syncthreads();

        // S = Q K^T for this 64x64 tile (4x4 per thread)
        float Sa[4][4];
#pragma unroll
        for (int i = 0; i < 4; ++i)
#pragma unroll
            for (int j = 0; j < 4; ++j) Sa[i][j] = 0.f;
#pragma unroll
        for (int h = 0; h < 64; ++h) {
            float qf[4], kf[4];
            *(float4*)&qf[0] = *(const float4*)&sQ[h * 68 + ty * 4];
            *(float4*)&kf[0] = *(const float4*)&sK[h * 68 + tx * 4];
#pragma unroll
            for (int i = 0; i < 4; ++i)
#pragma unroll
                for (int j = 0; j < 4; ++j)
                    Sa[i][j] = fmaf(qf[i], kf[j], Sa[i][j]);
        }

        // mask
#pragma unroll
        for (int i = 0; i < 4; ++i) {
            const int4 mv = *(const int4*)&mask[(b * TT + q0 + ty * 4 + i) * TT + s0 + tx * 4];
            Sa[i][0] = mv.x ? Sa[i][0] : -1.0e9f;
            Sa[i][1] = mv.y ? Sa[i][1] : -1.0e9f;
            Sa[i][2] = mv.z ? Sa[i][2] : -1.0e9f;
            Sa[i][3] = mv.w ? Sa[i][3] : -1.0e9f;
        }

        // online softmax update (rows reduced across the 16 tx lanes)
#pragma unroll
        for (int i = 0; i < 4; ++i) {
            float rm = fmaxf(fmaxf(Sa[i][0], Sa[i][1]), fmaxf(Sa[i][2], Sa[i][3]));
#pragma unroll
            for (int msk = 8; msk; msk >>= 1)
                rm = fmaxf(rm, __shfl_xor_sync(0xffffffffu, rm, msk));
            float mn = fmaxf(m_i[i], rm);
            float f  = __expf(m_i[i] - mn);
            m_i[i] = mn;
            float rs = 0.f;
#pragma unroll
            for (int j = 0; j < 4; ++j) {
                float p = __expf(Sa[i][j] - mn);
                Sa[i][j] = p;
                rs += p;
            }
#pragma unroll
            for (int msk = 8; msk; msk >>= 1)
                rs += __shfl_xor_sync(0xffffffffu, rs, msk);
            l_i[i] = l_i[i] * f + rs;
#pragma unroll
            for (int j = 0; j < 4; ++j) acc[i][j] *= f;
        }

        // write P transposed: sP[s][r]
#pragma unroll
        for (int i = 0; i < 4; ++i)
#pragma unroll
            for (int j = 0; j < 4; ++j)
                sP[(tx * 4 + j) * 68 + ty * 4 + i] = Sa[i][j];
        __syncthreads();

        // O += P V
#pragma unroll
        for (int s = 0; s < 64; ++s) {
            float pf[4], vf[4];
            *(float4*)&pf[0] = *(const float4*)&sP[s * 68 + ty * 4];
            *(float4*)&vf[0] = *(const float4*)&sV[s * 64 + tx * 4];
#pragma unroll
            for (int i = 0; i < 4; ++i)
#pragma unroll
                for (int j = 0; j < 4; ++j)
                    acc[i][j] = fmaf(pf[i], vf[j], acc[i][j]);
        }
        __syncthreads();
    }

    // normalize + store
#pragma unroll
    for (int i = 0; i < 4; ++i) {
        float inv = 1.0f / l_i[i];
        float4 o = make_float4(acc[i][0] * inv, acc[i][1] * inv,
                               acc[i][2] * inv, acc[i][3] * inv);
        *(float4*)&g_attn[((b * TT + q0 + ty * 4 + i) * NH + n) * HD + tx * 4] = o;
    }
}

// ---------------------------------------------------------------------------
// Output projection GEMM (NT): out = attn @ wo^T + bo
// attn: [4096,1024], wo: [1024(d), 1024(nh)] -> out[m][d] = sum_k attn[m][k]*wo[d][k]
// ---------------------------------------------------------------------------
__global__ __launch_bounds__(256) void out_gemm_kernel(
    const float* __restrict__ Wo, const float* __restrict__ Bo,
    float* __restrict__ Out)
{
    __shared__ float As[16][132];
    __shared__ float Bs[16][128];

    const int tid = threadIdx.x;
    const int tx = tid & 15, ty = tid >> 4;
    const int row0 = blockIdx.y * 128;
    const int col0 = blockIdx.x * 128;

    float acc[8][8];
#pragma unroll
    for (int i = 0; i < 8; ++i)
#pragma unroll
        for (int j = 0; j < 8; ++j) acc[i][j] = 0.f;

    for (int k0 = 0; k0 < 1024; k0 += 16) {
#pragma unroll
        for (int it = 0; it < 2; ++it) {
            int idx = tid + it * 256;
            int ar = idx >> 2, ak = (idx & 3) << 2;
            float4 a = *(const float4*)&g_attn[(row0 + ar) * 1024 + k0 + ak];
            As[ak + 0][ar] = a.x; As[ak + 1][ar] = a.y;
            As[ak + 2][ar] = a.z; As[ak + 3][ar] = a.w;
            // NT: Bs[k][n] = Wo[col0+n][k]
            int bn = idx >> 2, bk = (idx & 3) << 2;
            float4 w = *(const float4*)&Wo[(col0 + bn) * 1024 + k0 + bk];
            Bs[bk + 0][bn] = w.x; Bs[bk + 1][bn] = w.y;
            Bs[bk + 2][bn] = w.z; Bs[bk + 3][bn] = w.w;
        }
        __syncthreads();
#pragma unroll
        for (int kk = 0; kk < 16; ++kk) {
            float a[8], b[8];
            *(float4*)&a[0] = *(const float4*)&As[kk][ty * 8];
            *(float4*)&a[4] = *(const float4*)&As[kk][ty * 8 + 4];
            *(float4*)&b[0] = *(const float4*)&Bs[kk][tx * 8];
            *(float4*)&b[4] = *(const float4*)&Bs[kk][tx * 8 + 4];
#pragma unroll
            for (int i = 0; i < 8; ++i)
#pragma unroll
                for (int j = 0; j < 8; ++j)
                    acc[i][j] = fmaf(a[i], b[j], acc[i][j]);
        }
        __syncthreads();
    }

    float bb[8];
#pragma unroll
    for (int j = 0; j < 8; ++j) bb[j] = Bo[col0 + tx * 8 + j];
#pragma unroll
    for (int i = 0; i < 8; ++i) {
        int row = row0 + ty * 8 + i;
        float o[8];
#pragma unroll
        for (int j = 0; j < 8; ++j) o[j] = acc[i][j] + bb[j];
        *(float4*)&Out[row * 1024 + col0 + tx * 8]     = make_float4(o[0], o[1], o[2], o[3]);
        *(float4*)&Out[row * 1024 + col0 + tx * 8 + 4] = make_float4(o[4], o[5], o[6], o[7]);
    }
}

// ---------------------------------------------------------------------------
// Launch
// ---------------------------------------------------------------------------
extern "C" void kernel_launch(void* const* d_in, const int* in_sizes, int n_in,
                              void* d_out, int out_size)
{
    const float* x    = (const float*)d_in[0];
    const int*   mask = (const int*)  d_in[1];
    const float* wq   = (const float*)d_in[2];
    const float* bq   = (const float*)d_in[3];
    const float* wk   = (const float*)d_in[4];
    const float* bk   = (const float*)d_in[5];
    const float* wv   = (const float*)d_in[6];
    const float* bv   = (const float*)d_in[7];
    const float* wo   = (const float*)d_in[8];
    const float* bo   = (const float*)d_in[9];
    const float* pds  = (const float*)d_in[10];
    float* out = (float*)d_out;

    const int attn_smem = (64 * 68 * 3 + 64 * 64) * (int)sizeof(float);  // 68608 B
    cudaFuncSetAttribute(attn_kernel, cudaFuncAttributeMaxDynamicSharedMemorySize, attn_smem);

    qkv_gemm_kernel<<<dim3(8, 32, 3), 256>>>(x, wq, wk, wv, bq, bk, bv, pds);
    attn_kernel<<<dim3(32, 16, 2), 256, attn_smem>>>(mask);
    out_gemm_kernel<<<dim3(8, 32), 256>>>(wo, bo, out);
}